// round 15
// baseline (speedup 1.0000x reference)
#include <cuda_runtime.h>
#include <cuda_bf16.h>
#include <cstdint>

#define ND 50000
#define ED 800000
#define DD 128
#define NT 196   // (ND + 255) / 256 scan tiles

// ---------------- scratch (device globals; zero-initialized at load) ----------
__device__ int          g_cnt[ND];
__device__ float        g_dinv[ND];
__device__ int          g_off[ND + 1];
__device__ int          g_cur[ND];
__device__ unsigned int g_state[NT];   // decoupled-lookback: (flag<<30)|value
__device__ int          g_csr_src[ED];
__device__ float        g_h[ND * DD];
__device__ float        g_t[ND * DD];
__device__ float        g_stats[512];  // [0:256) layer1 sum/sumsq, [256:512) layer2

// ---------------- f32x2 / async helpers ----------------
__device__ __forceinline__ unsigned long long ffma2(unsigned long long a,
                                                    unsigned long long b,
                                                    unsigned long long c) {
    unsigned long long d;
    asm("fma.rn.f32x2 %0, %1, %2, %3;" : "=l"(d) : "l"(a), "l"(b), "l"(c));
    return d;
}
__device__ __forceinline__ unsigned long long pack2(float v) {
    unsigned long long d;
    asm("mov.b64 %0, {%1, %1};" : "=l"(d) : "f"(v));
    return d;
}
__device__ __forceinline__ void unpack2(unsigned long long v, float& lo, float& hi) {
    asm("mov.b64 {%0, %1}, %2;" : "=f"(lo), "=f"(hi) : "l"(v));
}
__device__ __forceinline__ unsigned int smem_u32(const void* p) {
    return (unsigned int)__cvta_generic_to_shared(p);
}
__device__ __forceinline__ void cp_async16(unsigned int s, const void* g) {
    asm volatile("cp.async.ca.shared.global [%0], [%1], 16;" :: "r"(s), "l"(g));
}

// ---------------- GEMM body: 8x8 micro-tiles, FFMA2, full double-buffer ------
// 256 threads as 16(ty) x 16(tx); block tile 128 rows x 128 cols.
// Both X and W double-buffered; ONE __syncthreads per k-tile; W via cp.async.
#define KTP 132   // padded row length for sXT/sW
__device__ __forceinline__ void gemm_body(int bid, const float* __restrict__ X,
                                          const float* __restrict__ W,
                                          float* __restrict__ H, int nrows,
                                          const float* __restrict__ stats,
                                          const float* __restrict__ gamma,
                                          const float* __restrict__ beta,
                                          float inv_n) {
    __shared__ float sXT[2][16 * KTP];    // [buf][k][row], 2 x 8.4 KB
    __shared__ float sW[2][16 * KTP];     // [buf][k][col], 2 x 8.4 KB
    __shared__ float sSc[DD], sSh[DD];
    int tid = threadIdx.x;
    int tx = tid & 15, ty = tid >> 4;
    int row0 = bid * 128;

    bool bn = (stats != nullptr);
    if (bn) {
        if (tid < DD) {
            float mu = stats[tid] * inv_n;
            float var = stats[DD + tid] * inv_n - mu * mu;
            float rstd = rsqrtf(var + 1e-5f);
            float sc = __ldg(gamma + tid) * rstd;
            sSc[tid] = sc;
            sSh[tid] = __ldg(beta + tid) - mu * sc;
        }
        __syncthreads();
    }

    const float4* Wf4 = reinterpret_cast<const float4*>(W);
    int r0s = tid >> 2, kk = tid & 3;             // X staging coords (i = tid)
    int r1s = (tid + 256) >> 2;                   // i = tid + 256 (same kk)
    int wk0 = tid >> 5, wc0 = tid & 31;           // W staging coords (i = tid)
    int wk1 = (tid + 256) >> 5;                   // i = tid + 256 (same wc)

    // ---- prologue: issue W0 (cp.async), load X0 to regs ----
    cp_async16(smem_u32(&sW[0][wk0 * KTP + wc0 * 4]), Wf4 + wk0 * 32 + wc0);
    cp_async16(smem_u32(&sW[0][wk1 * KTP + wc0 * 4]), Wf4 + wk1 * 32 + wc0);
    asm volatile("cp.async.commit_group;");
    float4 xreg[2];
#pragma unroll
    for (int j = 0; j < 2; j++) {
        int r = (j == 0) ? r0s : r1s;
        xreg[j] = make_float4(0.f, 0.f, 0.f, 0.f);
        if (row0 + r < nrows)
            xreg[j] = __ldg(reinterpret_cast<const float4*>(X) + (size_t)(row0 + r) * 32 + kk);
    }

    unsigned long long acc[4][8];
#pragma unroll
    for (int p = 0; p < 4; p++)
#pragma unroll
        for (int c = 0; c < 8; c++) acc[p][c] = 0ull;

    for (int kt = 0; kt < 8; kt++) {
        int buf = kt & 1;
        // stage X_kt (regs -> sXT[buf], transform + transpose)
#pragma unroll
        for (int j = 0; j < 2; j++) {
            int r = (j == 0) ? r0s : r1s;
            float4 v = xreg[j];
            if (bn) {
                float4 sc = reinterpret_cast<const float4*>(sSc)[kt * 4 + kk];
                float4 sh = reinterpret_cast<const float4*>(sSh)[kt * 4 + kk];
                v.x = fmaxf(fmaf(v.x, sc.x, sh.x), 0.f);
                v.y = fmaxf(fmaf(v.y, sc.y, sh.y), 0.f);
                v.z = fmaxf(fmaf(v.z, sc.z, sh.z), 0.f);
                v.w = fmaxf(fmaf(v.w, sc.w, sh.w), 0.f);
            }
            float* xb = sXT[buf];
            xb[(kk * 4 + 0) * KTP + r] = v.x;
            xb[(kk * 4 + 1) * KTP + r] = v.y;
            xb[(kk * 4 + 2) * KTP + r] = v.z;
            xb[(kk * 4 + 3) * KTP + r] = v.w;
        }
        // prefetch X_{kt+1} to regs (no smem hazard)
        if (kt < 7) {
#pragma unroll
            for (int j = 0; j < 2; j++) {
                int r = (j == 0) ? r0s : r1s;
                xreg[j] = make_float4(0.f, 0.f, 0.f, 0.f);
                if (row0 + r < nrows)
                    xreg[j] = __ldg(reinterpret_cast<const float4*>(X) +
                                    (size_t)(row0 + r) * 32 + (kt + 1) * 4 + kk);
            }
        }
        asm volatile("cp.async.wait_group 0;");   // W_kt landed
        __syncthreads();                           // X_kt visible; compute(kt-1) done
        // issue W_{kt+1} into the other buffer (all reads of it finished)
        if (kt < 7) {
            cp_async16(smem_u32(&sW[buf ^ 1][wk0 * KTP + wc0 * 4]),
                       Wf4 + ((kt + 1) * 16 + wk0) * 32 + wc0);
            cp_async16(smem_u32(&sW[buf ^ 1][wk1 * KTP + wc0 * 4]),
                       Wf4 + ((kt + 1) * 16 + wk1) * 32 + wc0);
            asm volatile("cp.async.commit_group;");
        }
        const float* wbuf = sW[buf];
        const float* xbuf = sXT[buf];
#pragma unroll
        for (int k = 0; k < 16; k++) {
            ulonglong2 a01 = *reinterpret_cast<const ulonglong2*>(xbuf + k * KTP + ty * 8);
            ulonglong2 a23 = *reinterpret_cast<const ulonglong2*>(xbuf + k * KTP + ty * 8 + 4);
            float4 b0 = *reinterpret_cast<const float4*>(wbuf + k * KTP + tx * 8);
            float4 b1 = *reinterpret_cast<const float4*>(wbuf + k * KTP + tx * 8 + 4);
            unsigned long long wd[8];
            wd[0] = pack2(b0.x); wd[1] = pack2(b0.y);
            wd[2] = pack2(b0.z); wd[3] = pack2(b0.w);
            wd[4] = pack2(b1.x); wd[5] = pack2(b1.y);
            wd[6] = pack2(b1.z); wd[7] = pack2(b1.w);
            unsigned long long ap[4] = {a01.x, a01.y, a23.x, a23.y};
#pragma unroll
            for (int p = 0; p < 4; p++)
#pragma unroll
                for (int c = 0; c < 8; c++)
                    acc[p][c] = ffma2(ap[p], wd[c], acc[p][c]);
        }
        // no trailing barrier: buffers alternate; next barrier fences reuse.
    }

    // store: pair p covers rows (ty*8 + 2p, ty*8 + 2p + 1), cols tx*8..tx*8+8
#pragma unroll
    for (int p = 0; p < 4; p++) {
        int re = row0 + ty * 8 + 2 * p;
        float lo[8], hi[8];
#pragma unroll
        for (int c = 0; c < 8; c++) unpack2(acc[p][c], lo[c], hi[c]);
        if (re < nrows) {
            float4* dst0 = reinterpret_cast<float4*>(H + (size_t)re * DD) + tx * 2;
            dst0[0] = make_float4(lo[0], lo[1], lo[2], lo[3]);
            dst0[1] = make_float4(lo[4], lo[5], lo[6], lo[7]);
        }
        if (re + 1 < nrows) {
            float4* dst1 = reinterpret_cast<float4*>(H + (size_t)(re + 1) * DD) + tx * 2;
            dst1[0] = make_float4(hi[0], hi[1], hi[2], hi[3]);
            dst1[1] = make_float4(hi[4], hi[5], hi[6], hi[7]);
        }
    }
}

// ---------------- hybrid: GEMM1 tiles first, then degcnt rider blocks --------
__global__ __launch_bounds__(256, 2) void k_gemm1_deg(const float* __restrict__ X,
                                                      const float* __restrict__ W,
                                                      float* __restrict__ H, int nrows,
                                                      const int* __restrict__ dst, int e,
                                                      int ngemm) {
    if ((int)blockIdx.x < ngemm) {
        gemm_body(blockIdx.x, X, W, H, nrows, nullptr, nullptr, nullptr, 0.f);
        return;
    }
    int tid = threadIdx.x;
    int pb = blockIdx.x - ngemm;
    if (pb == 0) {
        g_stats[tid] = 0.f;
        g_stats[256 + tid] = 0.f;
        if (tid < NT) g_state[tid] = 0u;
    }
    int nprep = gridDim.x - ngemm;
    for (int i = pb * 256 + tid; i < e; i += nprep * 256)
        atomicAdd(&g_cnt[dst[i]], 1);
}

// ---------------- standalone GEMM (layer 2, BN1+ReLU fused on input) ---------
__global__ __launch_bounds__(256, 2) void k_gemm(const float* __restrict__ X,
                                                 const float* __restrict__ W,
                                                 float* __restrict__ H, int nrows,
                                                 const float* __restrict__ stats,
                                                 const float* __restrict__ gamma,
                                                 const float* __restrict__ beta,
                                                 float inv_n) {
    gemm_body(blockIdx.x, X, W, H, nrows, stats, gamma, beta, inv_n);
}

// ---------------- single-pass scan: decoupled lookback -----------------------
__global__ __launch_bounds__(256) void k_scan(int n, int nt) {
    __shared__ int sm[256];
    __shared__ int s_prefix;
    int tid = threadIdx.x;
    int tile = blockIdx.x;
    int i = tile * 256 + tid;
    int d = (i < n) ? g_cnt[i] : 0;
    sm[tid] = d;
    __syncthreads();
    for (int off = 1; off < 256; off <<= 1) {
        int v = (tid >= off) ? sm[tid - off] : 0;
        __syncthreads();
        sm[tid] += v;
        __syncthreads();
    }
    int total = sm[255];
    if (tid == 255) {
        unsigned int flag = (tile == 0) ? 2u : 1u;
        atomicExch(&g_state[tile], (flag << 30) | (unsigned int)total);
    }
    if (tid < 32) {
        int running = 0;
        if (tile > 0) {
            int p = tile - 1;
            bool done = false;
            while (!done) {
                int idx = p - tid;
                unsigned int st = (idx >= 0) ? atomicAdd(&g_state[idx], 0u)
                                             : (2u << 30);
                unsigned int flag = st >> 30;
                int val = (int)(st & 0x3FFFFFFFu);
                unsigned validm = __ballot_sync(0xffffffffu, flag != 0u);
                unsigned prefm  = __ballot_sync(0xffffffffu, flag == 2u);
                if (prefm != 0u) {
                    int fp = __ffs(prefm) - 1;
                    unsigned below = (fp == 0) ? 0u : ((1u << fp) - 1u);
                    if ((validm & below) == below) {
                        int contrib = (tid <= fp) ? val : 0;
#pragma unroll
                        for (int o = 16; o; o >>= 1)
                            contrib += __shfl_xor_sync(0xffffffffu, contrib, o);
                        running += contrib;
                        done = true;
                    }
                } else if (validm == 0xffffffffu) {
                    int contrib = val;
#pragma unroll
                    for (int o = 16; o; o >>= 1)
                        contrib += __shfl_xor_sync(0xffffffffu, contrib, o);
                    running += contrib;
                    p -= 32;
                }
            }
        }
        if (tid == 0) s_prefix = running;
    }
    __syncthreads();
    int run = s_prefix;
    if (tid == 255 && tile > 0)
        atomicExch(&g_state[tile], (2u << 30) | (unsigned int)(run + total));
    if (i < n) {
        int o = run + sm[tid] - d;
        g_off[i] = o;
        g_cur[i] = o;
        g_dinv[i] = rsqrtf((float)(g_cnt[i] + 1));
    }
    if (tile == nt - 1 && tid == 255) g_off[n] = run + total;
}

// ---------------- fill CSR (counting sort by dst) ----------------------------
__global__ void k_fill(const int* __restrict__ src, const int* __restrict__ dst, int e) {
    int i = blockIdx.x * blockDim.x + threadIdx.x;
    if (i >= e) return;
    int s = src[i], d = dst[i];
    int pos = atomicAdd(&g_cur[d], 1);
    g_csr_src[pos] = s;
}

// ---------------- CSR pull aggregation: warp-per-node, float4 lanes, MLP-8 ----
__global__ __launch_bounds__(256) void k_agg(const float* __restrict__ H,
                                             const float* __restrict__ bias,
                                             float* __restrict__ T,
                                             float* __restrict__ stats, int n) {
    __shared__ float ssum[DD];
    __shared__ float ssq[DD];
    int tid = threadIdx.x;
    int warp = tid >> 5, lane = tid & 31;
    if (tid < DD) { ssum[tid] = 0.f; ssq[tid] = 0.f; }
    __syncthreads();

    float4 b4 = __ldg(reinterpret_cast<const float4*>(bias) + lane);
    float ls[4] = {0.f, 0.f, 0.f, 0.f}, lq[4] = {0.f, 0.f, 0.f, 0.f};
    int base = blockIdx.x * 32 + warp * 4;

#pragma unroll
    for (int nn = 0; nn < 4; nn++) {
        int d = base + nn;
        if (d >= n) break;
        float di = __ldg(g_dinv + d);
        float4 acc = __ldg(reinterpret_cast<const float4*>(H + (size_t)d * DD) + lane);
        float sw = di * di;
        acc.x = fmaf(acc.x, sw, b4.x);
        acc.y = fmaf(acc.y, sw, b4.y);
        acc.z = fmaf(acc.z, sw, b4.z);
        acc.w = fmaf(acc.w, sw, b4.w);
        int j = __ldg(g_off + d);
        int j1 = __ldg(g_off + d + 1);
        for (; j + 8 <= j1; j += 8) {
            int s0 = __ldg(g_csr_src + j);
            int s1 = __ldg(g_csr_src + j + 1);
            int s2 = __ldg(g_csr_src + j + 2);
            int s3 = __ldg(g_csr_src + j + 3);
            int s4 = __ldg(g_csr_src + j + 4);
            int s5 = __ldg(g_csr_src + j + 5);
            int s6 = __ldg(g_csr_src + j + 6);
            int s7 = __ldg(g_csr_src + j + 7);
            float n0 = __ldg(g_dinv + s0) * di;
            float n1 = __ldg(g_dinv + s1) * di;
            float n2 = __ldg(g_dinv + s2) * di;
            float n3 = __ldg(g_dinv + s3) * di;
            float n4 = __ldg(g_dinv + s4) * di;
            float n5 = __ldg(g_dinv + s5) * di;
            float n6 = __ldg(g_dinv + s6) * di;
            float n7 = __ldg(g_dinv + s7) * di;
            float4 v0 = __ldg(reinterpret_cast<const float4*>(H + (size_t)s0 * DD) + lane);
            float4 v1 = __ldg(reinterpret_cast<const float4*>(H + (size_t)s1 * DD) + lane);
            float4 v2 = __ldg(reinterpret_cast<const float4*>(H + (size_t)s2 * DD) + lane);
            float4 v3 = __ldg(reinterpret_cast<const float4*>(H + (size_t)s3 * DD) + lane);
            float4 v4 = __ldg(reinterpret_cast<const float4*>(H + (size_t)s4 * DD) + lane);
            float4 v5 = __ldg(reinterpret_cast<const float4*>(H + (size_t)s5 * DD) + lane);
            float4 v6 = __ldg(reinterpret_cast<const float4*>(H + (size_t)s6 * DD) + lane);
            float4 v7 = __ldg(reinterpret_cast<const float4*>(H + (size_t)s7 * DD) + lane);
            acc.x = fmaf(v0.x, n0, acc.x); acc.y = fmaf(v0.y, n0, acc.y);
            acc.z = fmaf(v0.z, n0, acc.z); acc.w = fmaf(v0.w, n0, acc.w);
            acc.x = fmaf(v1.x, n1, acc.x); acc.y = fmaf(v1.y, n1, acc.y);
            acc.z = fmaf(v1.z, n1, acc.z); acc.w = fmaf(v1.w, n1, acc.w);
            acc.x = fmaf(v2.x, n2, acc.x); acc.y = fmaf(v2.y, n2, acc.y);
            acc.z = fmaf(v2.z, n2, acc.z); acc.w = fmaf(v2.w, n2, acc.w);
            acc.x = fmaf(v3.x, n3, acc.x); acc.y = fmaf(v3.y, n3, acc.y);
            acc.z = fmaf(v3.z, n3, acc.z); acc.w = fmaf(v3.w, n3, acc.w);
            acc.x = fmaf(v4.x, n4, acc.x); acc.y = fmaf(v4.y, n4, acc.y);
            acc.z = fmaf(v4.z, n4, acc.z); acc.w = fmaf(v4.w, n4, acc.w);
            acc.x = fmaf(v5.x, n5, acc.x); acc.y = fmaf(v5.y, n5, acc.y);
            acc.z = fmaf(v5.z, n5, acc.z); acc.w = fmaf(v5.w, n5, acc.w);
            acc.x = fmaf(v6.x, n6, acc.x); acc.y = fmaf(v6.y, n6, acc.y);
            acc.z = fmaf(v6.z, n6, acc.z); acc.w = fmaf(v6.w, n6, acc.w);
            acc.x = fmaf(v7.x, n7, acc.x); acc.y = fmaf(v7.y, n7, acc.y);
            acc.z = fmaf(v7.z, n7, acc.z); acc.w = fmaf(v7.w, n7, acc.w);
        }
        for (; j < j1; j++) {
            int s = __ldg(g_csr_src + j);
            float nm = __ldg(g_dinv + s) * di;
            float4 v = __ldg(reinterpret_cast<const float4*>(H + (size_t)s * DD) + lane);
            acc.x = fmaf(v.x, nm, acc.x); acc.y = fmaf(v.y, nm, acc.y);
            acc.z = fmaf(v.z, nm, acc.z); acc.w = fmaf(v.w, nm, acc.w);
        }
        *(reinterpret_cast<float4*>(T + (size_t)d * DD) + lane) = acc;
        ls[0] += acc.x; ls[1] += acc.y; ls[2] += acc.z; ls[3] += acc.w;
        lq[0] += acc.x * acc.x; lq[1] += acc.y * acc.y;
        lq[2] += acc.z * acc.z; lq[3] += acc.w * acc.w;
    }
#pragma unroll
    for (int c = 0; c < 4; c++) {
        atomicAdd(&ssum[lane * 4 + c], ls[c]);
        atomicAdd(&ssq[lane * 4 + c], lq[c]);
    }
    __syncthreads();
    if (tid < DD) {
        atomicAdd(&stats[tid], ssum[tid]);
        atomicAdd(&stats[DD + tid], ssq[tid]);
    }
}

// ---------------- final: out = relu(bn2(t) + x); also re-zero g_cnt ----------
__global__ __launch_bounds__(256) void k_bnfinal(float* __restrict__ out,
                                                 const float* __restrict__ resid,
                                                 const float* __restrict__ stats,
                                                 const float* __restrict__ gamma,
                                                 const float* __restrict__ beta,
                                                 float inv_n, int n4, int n) {
    __shared__ float sSc[DD], sSh[DD];
    int tid = threadIdx.x;
    if (tid < DD) {
        float mu = stats[tid] * inv_n;
        float var = stats[DD + tid] * inv_n - mu * mu;
        float rstd = rsqrtf(var + 1e-5f);
        float sc = __ldg(gamma + tid) * rstd;
        sSc[tid] = sc;
        sSh[tid] = __ldg(beta + tid) - mu * sc;
    }
    __syncthreads();
    int i = blockIdx.x * blockDim.x + tid;
    if (i < n) g_cnt[i] = 0;   // invariant for next call (globals start zeroed)
    if (i >= n4) return;
    int c4 = i & 31;
    float4 sc = reinterpret_cast<const float4*>(sSc)[c4];
    float4 sh = reinterpret_cast<const float4*>(sSh)[c4];
    float4 t = reinterpret_cast<const float4*>(g_t)[i];
    float4 rv = __ldg(reinterpret_cast<const float4*>(resid) + i);
    float4 r;
    r.x = fmaxf(fmaf(t.x, sc.x, sh.x) + rv.x, 0.f);
    r.y = fmaxf(fmaf(t.y, sc.y, sh.y) + rv.y, 0.f);
    r.z = fmaxf(fmaf(t.z, sc.z, sh.z) + rv.z, 0.f);
    r.w = fmaxf(fmaf(t.w, sc.w, sh.w) + rv.w, 0.f);
    reinterpret_cast<float4*>(out)[i] = r;
}

extern "C" void kernel_launch(void* const* d_in, const int* in_sizes, int n_in,
                              void* d_out, int out_size) {
    const float* x   = (const float*)d_in[0];
    const int*   ei  = (const int*)d_in[1];
    const float* W1  = (const float*)d_in[2];
    const float* b1  = (const float*)d_in[3];
    const float* ga1 = (const float*)d_in[4];
    const float* be1 = (const float*)d_in[5];
    const float* W2  = (const float*)d_in[6];
    const float* b2  = (const float*)d_in[7];
    const float* ga2 = (const float*)d_in[8];
    const float* be2 = (const float*)d_in[9];
    float* out = (float*)d_out;

    int n = in_sizes[0] / DD;
    int e = in_sizes[1] / 2;
    const int* src = ei;
    const int* dst = ei + e;
    int n4 = n * (DD / 4);
    float inv_n = 1.0f / (float)n;

    float *d_h, *d_t, *d_stats;
    cudaGetSymbolAddress((void**)&d_h, g_h);
    cudaGetSymbolAddress((void**)&d_t, g_t);
    cudaGetSymbolAddress((void**)&d_stats, g_stats);
    float* stats1 = d_stats;
    float* stats2 = d_stats + 2 * DD;

    dim3 b256(256);
    int gN    = (n + 255) / 256;    // 196 == NT
    int gE    = (e + 255) / 256;
    int gGemm = (n + 127) / 128;    // 391
    int gAgg  = (n + 31) / 32;
    int gBn   = (n4 + 255) / 256;
    int nDeg  = 296;                // degcnt rider blocks (grid-stride)

    // ---- GEMM1 + degcnt in one launch (gemm blocks first) ----
    k_gemm1_deg<<<gGemm + nDeg, b256>>>(x, W1, d_h, n, dst, e, gGemm);

    // ---- remaining prep ----
    k_scan<<<gN, b256>>>(n, gN);
    k_fill<<<gE, b256>>>(src, dst, e);

    // ---- layer 1 aggregation ----
    k_agg<<<gAgg, b256>>>(d_h, b1, d_t, stats1, n);

    // ---- layer 2 (BN1+ReLU fused into GEMM2 input) ----
    k_gemm<<<gGemm, b256>>>(d_t, W2, d_h, n, stats1, ga1, be1, inv_n);
    k_agg<<<gAgg, b256>>>(d_h, b2, d_t, stats2, n);

    // ---- epilogue: BN2 + residual + relu (+ reset g_cnt for next call) ----
    k_bnfinal<<<gBn, b256>>>(out, x, stats2, ga2, be2, inv_n, n4, n);
}

// round 16
// speedup vs baseline: 1.5063x; 1.5063x over previous
#include <cuda_runtime.h>
#include <cuda_bf16.h>
#include <cstdint>

#define ND 50000
#define ED 800000
#define DD 128
#define NT 196   // (ND + 255) / 256 scan tiles

// ---------------- scratch (device globals; zero-initialized at load) ----------
__device__ int          g_cnt[ND];
__device__ float        g_dinv[ND];
__device__ int          g_off[ND + 1];
__device__ int          g_cur[ND];
__device__ unsigned int g_state[NT];   // decoupled-lookback: (flag<<30)|value
__device__ int          g_csr_src[ED];
__device__ float        g_h[ND * DD];
__device__ float        g_t[ND * DD];
__device__ float        g_stats[512];  // [0:256) layer1 sum/sumsq, [256:512) layer2

// ---------------- f32x2 / async helpers ----------------
__device__ __forceinline__ unsigned long long ffma2(unsigned long long a,
                                                    unsigned long long b,
                                                    unsigned long long c) {
    unsigned long long d;
    asm("fma.rn.f32x2 %0, %1, %2, %3;" : "=l"(d) : "l"(a), "l"(b), "l"(c));
    return d;
}
__device__ __forceinline__ unsigned long long pack2(float v) {
    unsigned long long d;
    asm("mov.b64 %0, {%1, %1};" : "=l"(d) : "f"(v));
    return d;
}
__device__ __forceinline__ void unpack2(unsigned long long v, float& lo, float& hi) {
    asm("mov.b64 {%0, %1}, %2;" : "=f"(lo), "=f"(hi) : "l"(v));
}
__device__ __forceinline__ unsigned int smem_u32(const void* p) {
    return (unsigned int)__cvta_generic_to_shared(p);
}
__device__ __forceinline__ void cp_async16(unsigned int s, const void* g) {
    asm volatile("cp.async.ca.shared.global [%0], [%1], 16;" :: "r"(s), "l"(g));
}

// ---------------- degcnt (+ zero stats & scan-state in block 0) --------------
__global__ void k_degcnt(const int* __restrict__ dst, int e) {
    int tid = threadIdx.x;
    if (blockIdx.x == 0) {
        g_stats[tid] = 0.f;
        g_stats[256 + tid] = 0.f;
        if (tid < NT) g_state[tid] = 0u;
    }
    int i = blockIdx.x * 256 + tid;
    if (i < e) atomicAdd(&g_cnt[dst[i]], 1);
}

// ---------------- single-pass scan: decoupled lookback -----------------------
__global__ __launch_bounds__(256) void k_scan(int n, int nt) {
    __shared__ int sm[256];
    __shared__ int s_prefix;
    int tid = threadIdx.x;
    int tile = blockIdx.x;
    int i = tile * 256 + tid;
    int d = (i < n) ? g_cnt[i] : 0;
    sm[tid] = d;
    __syncthreads();
    for (int off = 1; off < 256; off <<= 1) {
        int v = (tid >= off) ? sm[tid - off] : 0;
        __syncthreads();
        sm[tid] += v;
        __syncthreads();
    }
    int total = sm[255];
    if (tid == 255) {
        unsigned int flag = (tile == 0) ? 2u : 1u;
        atomicExch(&g_state[tile], (flag << 30) | (unsigned int)total);
    }
    if (tid < 32) {
        int running = 0;
        if (tile > 0) {
            int p = tile - 1;
            bool done = false;
            while (!done) {
                int idx = p - tid;
                unsigned int st = (idx >= 0) ? atomicAdd(&g_state[idx], 0u)
                                             : (2u << 30);
                unsigned int flag = st >> 30;
                int val = (int)(st & 0x3FFFFFFFu);
                unsigned validm = __ballot_sync(0xffffffffu, flag != 0u);
                unsigned prefm  = __ballot_sync(0xffffffffu, flag == 2u);
                if (prefm != 0u) {
                    int fp = __ffs(prefm) - 1;
                    unsigned below = (fp == 0) ? 0u : ((1u << fp) - 1u);
                    if ((validm & below) == below) {
                        int contrib = (tid <= fp) ? val : 0;
#pragma unroll
                        for (int o = 16; o; o >>= 1)
                            contrib += __shfl_xor_sync(0xffffffffu, contrib, o);
                        running += contrib;
                        done = true;
                    }
                } else if (validm == 0xffffffffu) {
                    int contrib = val;
#pragma unroll
                    for (int o = 16; o; o >>= 1)
                        contrib += __shfl_xor_sync(0xffffffffu, contrib, o);
                    running += contrib;
                    p -= 32;
                }
            }
        }
        if (tid == 0) s_prefix = running;
    }
    __syncthreads();
    int run = s_prefix;
    if (tid == 255 && tile > 0)
        atomicExch(&g_state[tile], (2u << 30) | (unsigned int)(run + total));
    if (i < n) {
        int o = run + sm[tid] - d;
        g_off[i] = o;
        g_cur[i] = o;
        g_dinv[i] = rsqrtf((float)(g_cnt[i] + 1));
    }
    if (tile == nt - 1 && tid == 255) g_off[n] = run + total;
}

// ---------------- fill CSR (counting sort by dst) ----------------------------
__global__ void k_fill(const int* __restrict__ src, const int* __restrict__ dst, int e) {
    int i = blockIdx.x * blockDim.x + threadIdx.x;
    if (i >= e) return;
    int s = src[i], d = dst[i];
    int pos = atomicAdd(&g_cur[d], 1);
    g_csr_src[pos] = s;
}

// ---------------- GEMM: 8x8 micro-tiles, FFMA2, full double-buffer ----------
// Block = 256 threads as 16(ty) x 16(tx); block tile 128 rows x 128 cols.
// Both X and W double-buffered; ONE __syncthreads per k-tile; W via cp.async.
#define KTP 132   // padded row length for sXT/sW
__global__ __launch_bounds__(256, 2) void k_gemm(const float* __restrict__ X,
                                                 const float* __restrict__ W,
                                                 float* __restrict__ H, int nrows,
                                                 const float* __restrict__ stats,
                                                 const float* __restrict__ gamma,
                                                 const float* __restrict__ beta,
                                                 float inv_n) {
    __shared__ float sXT[2][16 * KTP];    // [buf][k][row], 2 x 8.4 KB
    __shared__ float sW[2][16 * KTP];     // [buf][k][col], 2 x 8.4 KB
    __shared__ float sSc[DD], sSh[DD];
    int tid = threadIdx.x;
    int tx = tid & 15, ty = tid >> 4;
    int row0 = blockIdx.x * 128;

    bool bn = (stats != nullptr);
    if (bn) {
        if (tid < DD) {
            float mu = stats[tid] * inv_n;
            float var = stats[DD + tid] * inv_n - mu * mu;
            float rstd = rsqrtf(var + 1e-5f);
            float sc = __ldg(gamma + tid) * rstd;
            sSc[tid] = sc;
            sSh[tid] = __ldg(beta + tid) - mu * sc;
        }
        __syncthreads();
    }

    const float4* Wf4 = reinterpret_cast<const float4*>(W);
    int r0s = tid >> 2, kk = tid & 3;             // X staging coords (i = tid)
    int r1s = (tid + 256) >> 2;                   // i = tid + 256 (same kk)
    int wk0 = tid >> 5, wc0 = tid & 31;           // W staging coords (i = tid)
    int wk1 = (tid + 256) >> 5;                   // i = tid + 256 (same wc)

    // ---- prologue: issue W0 (cp.async), load X0 to regs ----
    cp_async16(smem_u32(&sW[0][wk0 * KTP + wc0 * 4]), Wf4 + wk0 * 32 + wc0);
    cp_async16(smem_u32(&sW[0][wk1 * KTP + wc0 * 4]), Wf4 + wk1 * 32 + wc0);
    asm volatile("cp.async.commit_group;");
    float4 xreg[2];
#pragma unroll
    for (int j = 0; j < 2; j++) {
        int r = (j == 0) ? r0s : r1s;
        xreg[j] = make_float4(0.f, 0.f, 0.f, 0.f);
        if (row0 + r < nrows)
            xreg[j] = __ldg(reinterpret_cast<const float4*>(X) + (size_t)(row0 + r) * 32 + kk);
    }

    unsigned long long acc[4][8];
#pragma unroll
    for (int p = 0; p < 4; p++)
#pragma unroll
        for (int c = 0; c < 8; c++) acc[p][c] = 0ull;

    for (int kt = 0; kt < 8; kt++) {
        int buf = kt & 1;
        // stage X_kt (regs -> sXT[buf], transform + transpose)
#pragma unroll
        for (int j = 0; j < 2; j++) {
            int r = (j == 0) ? r0s : r1s;
            float4 v = xreg[j];
            if (bn) {
                float4 sc = reinterpret_cast<const float4*>(sSc)[kt * 4 + kk];
                float4 sh = reinterpret_cast<const float4*>(sSh)[kt * 4 + kk];
                v.x = fmaxf(fmaf(v.x, sc.x, sh.x), 0.f);
                v.y = fmaxf(fmaf(v.y, sc.y, sh.y), 0.f);
                v.z = fmaxf(fmaf(v.z, sc.z, sh.z), 0.f);
                v.w = fmaxf(fmaf(v.w, sc.w, sh.w), 0.f);
            }
            float* xb = sXT[buf];
            xb[(kk * 4 + 0) * KTP + r] = v.x;
            xb[(kk * 4 + 1) * KTP + r] = v.y;
            xb[(kk * 4 + 2) * KTP + r] = v.z;
            xb[(kk * 4 + 3) * KTP + r] = v.w;
        }
        // prefetch X_{kt+1} to regs (no smem hazard)
        if (kt < 7) {
#pragma unroll
            for (int j = 0; j < 2; j++) {
                int r = (j == 0) ? r0s : r1s;
                xreg[j] = make_float4(0.f, 0.f, 0.f, 0.f);
                if (row0 + r < nrows)
                    xreg[j] = __ldg(reinterpret_cast<const float4*>(X) +
                                    (size_t)(row0 + r) * 32 + (kt + 1) * 4 + kk);
            }
        }
        asm volatile("cp.async.wait_group 0;");   // W_kt landed
        __syncthreads();                           // X_kt visible; compute(kt-1) done
        // issue W_{kt+1} into the other buffer (all reads of it finished)
        if (kt < 7) {
            cp_async16(smem_u32(&sW[buf ^ 1][wk0 * KTP + wc0 * 4]),
                       Wf4 + ((kt + 1) * 16 + wk0) * 32 + wc0);
            cp_async16(smem_u32(&sW[buf ^ 1][wk1 * KTP + wc0 * 4]),
                       Wf4 + ((kt + 1) * 16 + wk1) * 32 + wc0);
            asm volatile("cp.async.commit_group;");
        }
        const float* wbuf = sW[buf];
        const float* xbuf = sXT[buf];
#pragma unroll
        for (int k = 0; k < 16; k++) {
            ulonglong2 a01 = *reinterpret_cast<const ulonglong2*>(xbuf + k * KTP + ty * 8);
            ulonglong2 a23 = *reinterpret_cast<const ulonglong2*>(xbuf + k * KTP + ty * 8 + 4);
            float4 b0 = *reinterpret_cast<const float4*>(wbuf + k * KTP + tx * 8);
            float4 b1 = *reinterpret_cast<const float4*>(wbuf + k * KTP + tx * 8 + 4);
            unsigned long long wd[8];
            wd[0] = pack2(b0.x); wd[1] = pack2(b0.y);
            wd[2] = pack2(b0.z); wd[3] = pack2(b0.w);
            wd[4] = pack2(b1.x); wd[5] = pack2(b1.y);
            wd[6] = pack2(b1.z); wd[7] = pack2(b1.w);
            unsigned long long ap[4] = {a01.x, a01.y, a23.x, a23.y};
#pragma unroll
            for (int p = 0; p < 4; p++)
#pragma unroll
                for (int c = 0; c < 8; c++)
                    acc[p][c] = ffma2(ap[p], wd[c], acc[p][c]);
        }
        // no trailing barrier: buffers alternate; next barrier fences reuse.
    }

    // store: pair p covers rows (ty*8 + 2p, ty*8 + 2p + 1), cols tx*8..tx*8+8
#pragma unroll
    for (int p = 0; p < 4; p++) {
        int re = row0 + ty * 8 + 2 * p;
        float lo[8], hi[8];
#pragma unroll
        for (int c = 0; c < 8; c++) unpack2(acc[p][c], lo[c], hi[c]);
        if (re < nrows) {
            float4* dst0 = reinterpret_cast<float4*>(H + (size_t)re * DD) + tx * 2;
            dst0[0] = make_float4(lo[0], lo[1], lo[2], lo[3]);
            dst0[1] = make_float4(lo[4], lo[5], lo[6], lo[7]);
        }
        if (re + 1 < nrows) {
            float4* dst1 = reinterpret_cast<float4*>(H + (size_t)(re + 1) * DD) + tx * 2;
            dst1[0] = make_float4(hi[0], hi[1], hi[2], hi[3]);
            dst1[1] = make_float4(hi[4], hi[5], hi[6], hi[7]);
        }
    }
}

// ---------------- CSR pull aggregation: warp-per-node, float4 lanes, MLP-8 ----
__global__ __launch_bounds__(256) void k_agg(const float* __restrict__ H,
                                             const float* __restrict__ bias,
                                             float* __restrict__ T,
                                             float* __restrict__ stats, int n) {
    __shared__ float ssum[DD];
    __shared__ float ssq[DD];
    int tid = threadIdx.x;
    int warp = tid >> 5, lane = tid & 31;
    if (tid < DD) { ssum[tid] = 0.f; ssq[tid] = 0.f; }
    __syncthreads();

    float4 b4 = __ldg(reinterpret_cast<const float4*>(bias) + lane);
    float ls[4] = {0.f, 0.f, 0.f, 0.f}, lq[4] = {0.f, 0.f, 0.f, 0.f};
    int base = blockIdx.x * 32 + warp * 4;

#pragma unroll
    for (int nn = 0; nn < 4; nn++) {
        int d = base + nn;
        if (d >= n) break;
        float di = __ldg(g_dinv + d);
        float4 acc = __ldg(reinterpret_cast<const float4*>(H + (size_t)d * DD) + lane);
        float sw = di * di;
        acc.x = fmaf(acc.x, sw, b4.x);
        acc.y = fmaf(acc.y, sw, b4.y);
        acc.z = fmaf(acc.z, sw, b4.z);
        acc.w = fmaf(acc.w, sw, b4.w);
        int j = __ldg(g_off + d);
        int j1 = __ldg(g_off + d + 1);
        for (; j + 8 <= j1; j += 8) {
            int s0 = __ldg(g_csr_src + j);
            int s1 = __ldg(g_csr_src + j + 1);
            int s2 = __ldg(g_csr_src + j + 2);
            int s3 = __ldg(g_csr_src + j + 3);
            int s4 = __ldg(g_csr_src + j + 4);
            int s5 = __ldg(g_csr_src + j + 5);
            int s6 = __ldg(g_csr_src + j + 6);
            int s7 = __ldg(g_csr_src + j + 7);
            float n0 = __ldg(g_dinv + s0) * di;
            float n1 = __ldg(g_dinv + s1) * di;
            float n2 = __ldg(g_dinv + s2) * di;
            float n3 = __ldg(g_dinv + s3) * di;
            float n4 = __ldg(g_dinv + s4) * di;
            float n5 = __ldg(g_dinv + s5) * di;
            float n6 = __ldg(g_dinv + s6) * di;
            float n7 = __ldg(g_dinv + s7) * di;
            float4 v0 = __ldg(reinterpret_cast<const float4*>(H + (size_t)s0 * DD) + lane);
            float4 v1 = __ldg(reinterpret_cast<const float4*>(H + (size_t)s1 * DD) + lane);
            float4 v2 = __ldg(reinterpret_cast<const float4*>(H + (size_t)s2 * DD) + lane);
            float4 v3 = __ldg(reinterpret_cast<const float4*>(H + (size_t)s3 * DD) + lane);
            float4 v4 = __ldg(reinterpret_cast<const float4*>(H + (size_t)s4 * DD) + lane);
            float4 v5 = __ldg(reinterpret_cast<const float4*>(H + (size_t)s5 * DD) + lane);
            float4 v6 = __ldg(reinterpret_cast<const float4*>(H + (size_t)s6 * DD) + lane);
            float4 v7 = __ldg(reinterpret_cast<const float4*>(H + (size_t)s7 * DD) + lane);
            acc.x = fmaf(v0.x, n0, acc.x); acc.y = fmaf(v0.y, n0, acc.y);
            acc.z = fmaf(v0.z, n0, acc.z); acc.w = fmaf(v0.w, n0, acc.w);
            acc.x = fmaf(v1.x, n1, acc.x); acc.y = fmaf(v1.y, n1, acc.y);
            acc.z = fmaf(v1.z, n1, acc.z); acc.w = fmaf(v1.w, n1, acc.w);
            acc.x = fmaf(v2.x, n2, acc.x); acc.y = fmaf(v2.y, n2, acc.y);
            acc.z = fmaf(v2.z, n2, acc.z); acc.w = fmaf(v2.w, n2, acc.w);
            acc.x = fmaf(v3.x, n3, acc.x); acc.y = fmaf(v3.y, n3, acc.y);
            acc.z = fmaf(v3.z, n3, acc.z); acc.w = fmaf(v3.w, n3, acc.w);
            acc.x = fmaf(v4.x, n4, acc.x); acc.y = fmaf(v4.y, n4, acc.y);
            acc.z = fmaf(v4.z, n4, acc.z); acc.w = fmaf(v4.w, n4, acc.w);
            acc.x = fmaf(v5.x, n5, acc.x); acc.y = fmaf(v5.y, n5, acc.y);
            acc.z = fmaf(v5.z, n5, acc.z); acc.w = fmaf(v5.w, n5, acc.w);
            acc.x = fmaf(v6.x, n6, acc.x); acc.y = fmaf(v6.y, n6, acc.y);
            acc.z = fmaf(v6.z, n6, acc.z); acc.w = fmaf(v6.w, n6, acc.w);
            acc.x = fmaf(v7.x, n7, acc.x); acc.y = fmaf(v7.y, n7, acc.y);
            acc.z = fmaf(v7.z, n7, acc.z); acc.w = fmaf(v7.w, n7, acc.w);
        }
        for (; j < j1; j++) {
            int s = __ldg(g_csr_src + j);
            float nm = __ldg(g_dinv + s) * di;
            float4 v = __ldg(reinterpret_cast<const float4*>(H + (size_t)s * DD) + lane);
            acc.x = fmaf(v.x, nm, acc.x); acc.y = fmaf(v.y, nm, acc.y);
            acc.z = fmaf(v.z, nm, acc.z); acc.w = fmaf(v.w, nm, acc.w);
        }
        *(reinterpret_cast<float4*>(T + (size_t)d * DD) + lane) = acc;
        ls[0] += acc.x; ls[1] += acc.y; ls[2] += acc.z; ls[3] += acc.w;
        lq[0] += acc.x * acc.x; lq[1] += acc.y * acc.y;
        lq[2] += acc.z * acc.z; lq[3] += acc.w * acc.w;
    }
#pragma unroll
    for (int c = 0; c < 4; c++) {
        atomicAdd(&ssum[lane * 4 + c], ls[c]);
        atomicAdd(&ssq[lane * 4 + c], lq[c]);
    }
    __syncthreads();
    if (tid < DD) {
        atomicAdd(&stats[tid], ssum[tid]);
        atomicAdd(&stats[DD + tid], ssq[tid]);
    }
}

// ---------------- final: out = relu(bn2(t) + x); also re-zero g_cnt ----------
__global__ __launch_bounds__(256) void k_bnfinal(float* __restrict__ out,
                                                 const float* __restrict__ resid,
                                                 const float* __restrict__ stats,
                                                 const float* __restrict__ gamma,
                                                 const float* __restrict__ beta,
                                                 float inv_n, int n4, int n) {
    __shared__ float sSc[DD], sSh[DD];
    int tid = threadIdx.x;
    if (tid < DD) {
        float mu = stats[tid] * inv_n;
        float var = stats[DD + tid] * inv_n - mu * mu;
        float rstd = rsqrtf(var + 1e-5f);
        float sc = __ldg(gamma + tid) * rstd;
        sSc[tid] = sc;
        sSh[tid] = __ldg(beta + tid) - mu * sc;
    }
    __syncthreads();
    int i = blockIdx.x * blockDim.x + tid;
    if (i < n) g_cnt[i] = 0;   // invariant for next call (globals start zeroed)
    if (i >= n4) return;
    int c4 = i & 31;
    float4 sc = reinterpret_cast<const float4*>(sSc)[c4];
    float4 sh = reinterpret_cast<const float4*>(sSh)[c4];
    float4 t = reinterpret_cast<const float4*>(g_t)[i];
    float4 rv = __ldg(reinterpret_cast<const float4*>(resid) + i);
    float4 r;
    r.x = fmaxf(fmaf(t.x, sc.x, sh.x) + rv.x, 0.f);
    r.y = fmaxf(fmaf(t.y, sc.y, sh.y) + rv.y, 0.f);
    r.z = fmaxf(fmaf(t.z, sc.z, sh.z) + rv.z, 0.f);
    r.w = fmaxf(fmaf(t.w, sc.w, sh.w) + rv.w, 0.f);
    reinterpret_cast<float4*>(out)[i] = r;
}

extern "C" void kernel_launch(void* const* d_in, const int* in_sizes, int n_in,
                              void* d_out, int out_size) {
    const float* x   = (const float*)d_in[0];
    const int*   ei  = (const int*)d_in[1];
    const float* W1  = (const float*)d_in[2];
    const float* b1  = (const float*)d_in[3];
    const float* ga1 = (const float*)d_in[4];
    const float* be1 = (const float*)d_in[5];
    const float* W2  = (const float*)d_in[6];
    const float* b2  = (const float*)d_in[7];
    const float* ga2 = (const float*)d_in[8];
    const float* be2 = (const float*)d_in[9];
    float* out = (float*)d_out;

    int n = in_sizes[0] / DD;
    int e = in_sizes[1] / 2;
    const int* src = ei;
    const int* dst = ei + e;
    int n4 = n * (DD / 4);
    float inv_n = 1.0f / (float)n;

    float *d_h, *d_t, *d_stats;
    cudaGetSymbolAddress((void**)&d_h, g_h);
    cudaGetSymbolAddress((void**)&d_t, g_t);
    cudaGetSymbolAddress((void**)&d_stats, g_stats);
    float* stats1 = d_stats;
    float* stats2 = d_stats + 2 * DD;

    dim3 b256(256);
    int gN    = (n + 255) / 256;    // 196 == NT
    int gE    = (e + 255) / 256;
    int gGemm = (n + 127) / 128;    // 391
    int gAgg  = (n + 31) / 32;
    int gBn   = (n4 + 255) / 256;

    // secondary stream + fork/join events (created once; no device memory)
    static cudaStream_t s2 = nullptr;
    static cudaEvent_t evFork = nullptr, evJoin = nullptr;
    if (s2 == nullptr) {
        cudaStreamCreateWithFlags(&s2, cudaStreamNonBlocking);
        cudaEventCreateWithFlags(&evFork, cudaEventDisableTiming);
        cudaEventCreateWithFlags(&evJoin, cudaEventDisableTiming);
    }

    // ---- fork: prep chain on s2, GEMM1 on main stream (parallel branches) ----
    cudaEventRecord(evFork, 0);
    cudaStreamWaitEvent(s2, evFork, 0);

    k_degcnt<<<gE, b256, 0, s2>>>(dst, e);
    k_scan<<<gN, b256, 0, s2>>>(n, gN);
    k_fill<<<gE, b256, 0, s2>>>(src, dst, e);
    cudaEventRecord(evJoin, s2);

    k_gemm<<<gGemm, b256>>>(x, W1, d_h, n, nullptr, nullptr, nullptr, 0.f);

    // ---- join: agg1 needs both GEMM1 (main) and CSR (s2) ----
    cudaStreamWaitEvent(0, evJoin, 0);

    k_agg<<<gAgg, b256>>>(d_h, b1, d_t, stats1, n);

    // ---- layer 2 (BN1+ReLU fused into GEMM2 input) ----
    k_gemm<<<gGemm, b256>>>(d_t, W2, d_h, n, stats1, ga1, be1, inv_n);
    k_agg<<<gAgg, b256>>>(d_h, b2, d_t, stats2, n);

    // ---- epilogue: BN2 + residual + relu (+ reset g_cnt for next call) ----
    k_bnfinal<<<gBn, b256>>>(out, x, stats2, ga2, be2, inv_n, n4, n);
}